// round 11
// baseline (speedup 1.0000x reference)
#include <cuda_runtime.h>
#include <cuda_bf16.h>
#include <math.h>
#include <stdint.h>
#include <stddef.h>

// ---------------- problem constants ----------------
#define DMODEL 512
#define DINNER 1024
#define DSTATE 16
#define DTRANK 32
#define DFF    2048
#define BATCH  8
#define SEQ    4096
#define MROWS  (BATCH*SEQ)        // 32768

// ---------------- fp32 scratch ----------------
static const size_t SZ_XZ    = (size_t)MROWS * 2 * DINNER;
static const size_t SZ_XC    = (size_t)MROWS * DINNER;
static const size_t SZ_DBC   = (size_t)MROWS * 64;
static const size_t SZ_GATED = (size_t)MROWS * DINNER;
static const size_t SZ_M     = (size_t)MROWS * DMODEL;

__device__ float g_xz   [2ull * 67108864ull];
__device__ float g_xc   [2ull * 33554432ull];
__device__ float g_dbc  [2ull * 2097152ull];
__device__ float g_gated[2ull * 33554432ull];
__device__ float g_m    [2ull * 16777216ull];
__device__ float g_h    [16777216ull];
__device__ float g_ff   [67108864ull];
__device__ float g_ffo  [16777216ull];

// ---------------- bf16 split scratch (K' = 3K: A=[hi|hi|lo], B=[hi|lo|hi]) ----
__device__ __nv_bfloat16 g_x3   [50331648ull];            // 32768 x 1536
__device__ __nv_bfloat16 g_xc3  [2ull * 100663296ull];    // 32768 x 3072 per dir
__device__ __nv_bfloat16 g_g3   [2ull * 100663296ull];    // 32768 x 3072 per dir
__device__ __nv_bfloat16 g_h3   [50331648ull];            // 32768 x 1536
__device__ __nv_bfloat16 g_ff3  [201326592ull];           // 32768 x 6144
__device__ __nv_bfloat16 g_win3 [2ull * 3145728ull];      // 2048 x 1536
__device__ __nv_bfloat16 g_wxp3 [2ull * 196608ull];       // 64 x 3072
__device__ __nv_bfloat16 g_wou3 [2ull * 1572864ull];      // 512 x 3072
__device__ __nv_bfloat16 g_wf13 [3145728ull];             // 2048 x 1536
__device__ __nv_bfloat16 g_wf23 [3145728ull];             // 512 x 6144

static const size_t SZ_XC3 = 100663296ull;
static const size_t SZ_G3  = 100663296ull;
static const size_t SZ_WIN3 = 3145728ull;
static const size_t SZ_WXP3 = 196608ull;
static const size_t SZ_WOU3 = 1572864ull;

// ---------------- helpers ----------------
__device__ __forceinline__ float siluf(float v){
    return v / (1.f + __expf(-v));
}
__device__ __forceinline__ float gelu_tanh(float v){
    float u = 0.7978845608028654f * (v + 0.044715f * v * v * v);
    return 0.5f * v * (1.f + tanhf(u));
}

// mma.sync m16n8k16 bf16 -> f32 (baseline PTX, compiles for compute_103).
__device__ __forceinline__ void mma16816(float* d,
                                         const uint32_t* a, const uint32_t* b,
                                         const float* c)
{
    asm volatile(
        "mma.sync.aligned.m16n8k16.row.col.f32.bf16.bf16.f32 "
        "{%0,%1,%2,%3}, {%4,%5,%6,%7}, {%8,%9}, {%10,%11,%12,%13};\n"
        : "=f"(d[0]), "=f"(d[1]), "=f"(d[2]), "=f"(d[3])
        : "r"(a[0]), "r"(a[1]), "r"(a[2]), "r"(a[3]),
          "r"(b[0]), "r"(b[1]),
          "f"(c[0]), "f"(c[1]), "f"(c[2]), "f"(c[3]));
}

// ---------------- split3: fp32 [R][K] -> bf16 [R][3K] ----------------
// MODE 0 (A operand): [hi | hi | lo].  MODE 1 (B operand): [hi | lo | hi].
template<int MODE>
__global__ __launch_bounds__(256)
void split3_kernel(const float* __restrict__ s0, const float* __restrict__ s1,
                   __nv_bfloat16* __restrict__ d0, __nv_bfloat16* __restrict__ d1,
                   int K)
{
    const float* src = blockIdx.z ? s1 : s0;
    __nv_bfloat16* dst = blockIdx.z ? d1 : d0;
    const int k = blockIdx.x * 256 + threadIdx.x;
    const size_t r = blockIdx.y;
    float v = src[r * K + k];
    __nv_bfloat16 hi = __float2bfloat16(v);
    __nv_bfloat16 lo = __float2bfloat16(v - __bfloat162float(hi));
    size_t o = r * (size_t)(3 * K);
    if (MODE == 0){
        dst[o + k]         = hi;
        dst[o + K + k]     = hi;
        dst[o + 2*K + k]   = lo;
    } else {
        dst[o + k]         = hi;
        dst[o + K + k]     = lo;
        dst[o + 2*K + k]   = hi;
    }
}

// ---------------- mma.sync bf16 GEMM: C[M,N](f32) = A3[M,K3] * B3[N,K3]^T ----
// BM=128 rows, BN columns (128 or 64), BK=32. 256 threads = 8 warps (4m x 2n).
// Warp tile: 32 x (BN/2). Fragment layouts per PTX ISA m16n8k16 tables.
// SMEM row stride 40 bf16 (80B) -> conflict-free fragment loads.
// blockIdx.z selects operand set. EPI: 0 none, 1 +bias, 2 +bias+gelu.
template<int BN, int EPI>
__global__ __launch_bounds__(256)
void mma_gemm_kernel(const __nv_bfloat16* __restrict__ A0, const __nv_bfloat16* __restrict__ A1,
                     const __nv_bfloat16* __restrict__ B0, const __nv_bfloat16* __restrict__ B1,
                     float* __restrict__ C0, float* __restrict__ C1,
                     const float* __restrict__ bias0, const float* __restrict__ bias1,
                     int N, int K3)
{
    constexpr int BM = 128;
    constexpr int BK = 32;
    constexpr int STR = 40;                 // smem row stride in bf16 (80B)
    constexpr int WN  = BN / 2;             // warp n-width (64 or 32)
    constexpr int NT  = WN / 8;             // n-tiles per warp (8 or 4)
    constexpr int ALD = 2;                  // uint4 loads per thread (A tile)
    constexpr int BLD = (BN * BK) / (8 * 256);  // uint4 loads per thread (B tile)

    __shared__ __align__(16) __nv_bfloat16 sA[BM * STR];
    __shared__ __align__(16) __nv_bfloat16 sB[BN * STR];

    const int z = blockIdx.z;
    const __nv_bfloat16* A = z ? A1 : A0;
    const __nv_bfloat16* B = z ? B1 : B0;
    float*               C = z ? C1 : C0;
    const float*      bias = z ? bias1 : bias0;

    const int tid  = threadIdx.x;
    const int wid  = tid >> 5;
    const int lane = tid & 31;
    const int wm   = wid & 3;               // warp m index (0..3)
    const int wn   = wid >> 2;              // warp n index (0..1)
    const int m0 = blockIdx.y * BM;
    const int n0 = blockIdx.x * BN;

    uint4 aReg[ALD], bReg[BLD];

    auto loadA = [&](int k0){
        #pragma unroll
        for (int i = 0; i < ALD; i++){
            int lin = tid + i * 256;        // 0..511
            int r = lin >> 2, c8 = (lin & 3) * 8;
            aReg[i] = *(const uint4*)(A + (size_t)(m0 + r) * K3 + k0 + c8);
        }
    };
    auto loadB = [&](int k0){
        #pragma unroll
        for (int i = 0; i < BLD; i++){
            int lin = tid + i * 256;
            int r = lin >> 2, c8 = (lin & 3) * 8;
            bReg[i] = *(const uint4*)(B + (size_t)(n0 + r) * K3 + k0 + c8);
        }
    };
    auto storeA = [&](){
        #pragma unroll
        for (int i = 0; i < ALD; i++){
            int lin = tid + i * 256;
            int r = lin >> 2, c8 = (lin & 3) * 8;
            *(uint4*)(sA + r * STR + c8) = aReg[i];
        }
    };
    auto storeB = [&](){
        #pragma unroll
        for (int i = 0; i < BLD; i++){
            int lin = tid + i * 256;
            int r = lin >> 2, c8 = (lin & 3) * 8;
            *(uint4*)(sB + r * STR + c8) = bReg[i];
        }
    };

    float acc[2][NT][4];
    #pragma unroll
    for (int mt = 0; mt < 2; mt++)
        #pragma unroll
        for (int nt = 0; nt < NT; nt++)
            #pragma unroll
            for (int i = 0; i < 4; i++) acc[mt][nt][i] = 0.f;

    loadA(0); loadB(0);
    storeA(); storeB();
    __syncthreads();

    const int ktiles = K3 / BK;
    const int gid  = lane >> 2;             // group id 0..7
    const int tig2 = (lane & 3) * 2;        // 2*thread-in-group

    for (int t = 0; t < ktiles; t++){
        if (t + 1 < ktiles){ loadA((t+1)*BK); loadB((t+1)*BK); }

        #pragma unroll
        for (int kk = 0; kk < 2; kk++){
            const int kb = kk * 16 + tig2;
            // A fragments for both m-tiles
            uint32_t af[2][4];
            #pragma unroll
            for (int mt = 0; mt < 2; mt++){
                const int rb = wm * 32 + mt * 16 + gid;
                af[mt][0] = *(const uint32_t*)(sA + (rb    ) * STR + kb    );
                af[mt][1] = *(const uint32_t*)(sA + (rb + 8) * STR + kb    );
                af[mt][2] = *(const uint32_t*)(sA + (rb    ) * STR + kb + 8);
                af[mt][3] = *(const uint32_t*)(sA + (rb + 8) * STR + kb + 8);
            }
            // B fragments per n-tile, 2 MMAs each
            #pragma unroll
            for (int nt = 0; nt < NT; nt++){
                const int nb = wn * WN + nt * 8 + gid;
                uint32_t bf[2];
                bf[0] = *(const uint32_t*)(sB + nb * STR + kb    );
                bf[1] = *(const uint32_t*)(sB + nb * STR + kb + 8);
                mma16816(acc[0][nt], af[0], bf, acc[0][nt]);
                mma16816(acc[1][nt], af[1], bf, acc[1][nt]);
            }
        }
        __syncthreads();
        if (t + 1 < ktiles){ storeA(); storeB(); __syncthreads(); }
    }

    // ---- epilogue ----
    #pragma unroll
    for (int mt = 0; mt < 2; mt++){
        const int row = m0 + wm * 32 + mt * 16 + gid;
        #pragma unroll
        for (int nt = 0; nt < NT; nt++){
            const int col = n0 + wn * WN + nt * 8 + tig2;
            float v0 = acc[mt][nt][0], v1 = acc[mt][nt][1];
            float v2 = acc[mt][nt][2], v3 = acc[mt][nt][3];
            if (EPI >= 1){
                float b0 = __ldg(&bias[col]), b1 = __ldg(&bias[col + 1]);
                v0 += b0; v1 += b1; v2 += b0; v3 += b1;
            }
            if (EPI == 2){
                v0 = gelu_tanh(v0); v1 = gelu_tanh(v1);
                v2 = gelu_tanh(v2); v3 = gelu_tanh(v3);
            }
            float2 lo; lo.x = v0; lo.y = v1;
            float2 hi; hi.x = v2; hi.y = v3;
            *(float2*)(C + (size_t)row * N + col)       = lo;
            *(float2*)(C + (size_t)(row + 8) * N + col) = hi;
        }
    }
}

// ---------------- depthwise causal/anticausal conv(4) + bias + silu ----------------
__global__ __launch_bounds__(256)
void conv_silu_kernel(const float* __restrict__ cw0, const float* __restrict__ cb0,
                      const float* __restrict__ cw1, const float* __restrict__ cb1)
{
    const int c   = blockIdx.x * 256 + threadIdx.x;
    const int m   = blockIdx.y;
    const int dir = blockIdx.z;
    const float* cw = dir ? cw1 : cw0;
    const float* cb = dir ? cb1 : cb0;
    const float* xz = g_xz + (size_t)dir * SZ_XZ;

    const int b = m >> 12;
    const int l = m & (SEQ - 1);

    float w[4];
    #pragma unroll
    for (int j = 0; j < 4; j++) w[j] = __ldg(&cw[c*4 + j]);

    float acc = __ldg(&cb[c]);
    const size_t rowbase = (size_t)(b * SEQ) * (2*DINNER) + c;
    if (dir == 0){
        #pragma unroll
        for (int j = 0; j < 4; j++){
            int li = l - 3 + j;
            if (li >= 0) acc = fmaf(w[j], xz[rowbase + (size_t)li * (2*DINNER)], acc);
        }
    } else {
        #pragma unroll
        for (int j = 0; j < 4; j++){
            int li = l + 3 - j;
            if (li < SEQ) acc = fmaf(w[j], xz[rowbase + (size_t)li * (2*DINNER)], acc);
        }
    }
    g_xc[(size_t)dir * SZ_XC + (size_t)m * DINNER + c] = siluf(acc);
}

// ---------------- selective scan (fused dt-proj + softplus + scan + D + z-gate) ----
__global__ __launch_bounds__(256)
void scan_kernel(const float* __restrict__ dtw0, const float* __restrict__ dtb0,
                 const float* __restrict__ alog0, const float* __restrict__ D0,
                 const float* __restrict__ dtw1, const float* __restrict__ dtb1,
                 const float* __restrict__ alog1, const float* __restrict__ D1)
{
    const int dir = blockIdx.z;
    const int b   = blockIdx.y;
    const int cg  = blockIdx.x;
    const int tid = threadIdx.x;
    const int chl = tid >> 2;
    const int sub = tid & 3;
    const int c   = cg * 64 + chl;

    const float* dtw  = dir ? dtw1  : dtw0;
    const float* dtb  = dir ? dtb1  : dtb0;
    const float* alog = dir ? alog1 : alog0;
    const float* Dp   = dir ? D1    : D0;

    float A[4], w[8];
    #pragma unroll
    for (int i = 0; i < 4; i++) A[i] = -__expf(__ldg(&alog[c*DSTATE + sub*4 + i]));
    #pragma unroll
    for (int i = 0; i < 8; i++) w[i] = __ldg(&dtw[c*DTRANK + sub*8 + i]);
    const float dtb_c = __ldg(&dtb[c]);
    const float Dc    = __ldg(&Dp[c]);

    const float* dbc = g_dbc   + (size_t)dir * SZ_DBC   + (size_t)(b*SEQ) * 64;
    const float* xcb = g_xc    + (size_t)dir * SZ_XC    + (size_t)(b*SEQ) * DINNER;
    const float* zp  = g_xz    + (size_t)dir * SZ_XZ    + (size_t)(b*SEQ) * (2*DINNER) + DINNER;
    float*       op  = g_gated + (size_t)dir * SZ_GATED + (size_t)(b*SEQ) * DINNER;

    __shared__ float s_dbc[8][64];
    __shared__ float s_xc [8][64];

    float h[4] = {0.f, 0.f, 0.f, 0.f};

    for (int t0 = 0; t0 < SEQ; t0 += 8){
        __syncthreads();
        #pragma unroll
        for (int i = 0; i < 2; i++){
            int lin = tid + i * 256;
            int r = lin >> 6, col = lin & 63;
            int t = t0 + r;
            int l = dir ? (SEQ - 1 - t) : t;
            s_dbc[r][col] = dbc[(size_t)l * 64 + col];
            s_xc [r][col] = xcb[(size_t)l * DINNER + cg*64 + col];
        }
        __syncthreads();

        #pragma unroll
        for (int r = 0; r < 8; r++){
            int t = t0 + r;
            int l = dir ? (SEQ - 1 - t) : t;

            float dtp = 0.f;
            #pragma unroll
            for (int i = 0; i < 8; i++) dtp = fmaf(s_dbc[r][sub*8 + i], w[i], dtp);
            dtp += __shfl_xor_sync(0xffffffffu, dtp, 1);
            dtp += __shfl_xor_sync(0xffffffffu, dtp, 2);

            float v  = dtp + dtb_c;
            float dt = (v > 15.f) ? v : __logf(1.f + __expf(v));
            float xt  = s_xc[r][chl];
            float dtx = dt * xt;

            float yp = 0.f;
            #pragma unroll
            for (int i = 0; i < 4; i++){
                int n = sub*4 + i;
                float dA = __expf(dt * A[i]);
                h[i] = fmaf(dA, h[i], dtx * s_dbc[r][32 + n]);
                yp   = fmaf(h[i], s_dbc[r][48 + n], yp);
            }
            yp += __shfl_xor_sync(0xffffffffu, yp, 1);
            yp += __shfl_xor_sync(0xffffffffu, yp, 2);

            if (sub == 0){
                float y  = fmaf(xt, Dc, yp);
                float zv = __ldg(zp + (size_t)l * (2*DINNER) + c);
                op[(size_t)l * DINNER + c] = y * siluf(zv);
            }
        }
    }
}

// ---------------- combine: h = 0.5*(LN(x+mf;f) + LN(x+mb;b)) ----------------
__global__ __launch_bounds__(256)
void combine_ln_kernel(const float* __restrict__ x,
                       const float* __restrict__ gf, const float* __restrict__ bf,
                       const float* __restrict__ gb, const float* __restrict__ bb)
{
    const int warp = threadIdx.x >> 5, lane = threadIdx.x & 31;
    const size_t row = (size_t)blockIdx.x * 8 + warp;
    const float* xr  = x + row * DMODEL;
    const float* mfr = g_m + row * DMODEL;
    const float* mbr = g_m + SZ_M + row * DMODEL;

    float af[16], ab[16];
    float sf = 0.f, qf = 0.f, sb = 0.f, qb = 0.f;
    #pragma unroll
    for (int jj = 0; jj < 4; jj++){
        int col = lane*4 + jj*128;
        float4 xv = *(const float4*)(xr  + col);
        float4 fv = *(const float4*)(mfr + col);
        float4 bv = *(const float4*)(mbr + col);
        float* pf = &af[jj*4]; float* pb = &ab[jj*4];
        pf[0]=xv.x+fv.x; pf[1]=xv.y+fv.y; pf[2]=xv.z+fv.z; pf[3]=xv.w+fv.w;
        pb[0]=xv.x+bv.x; pb[1]=xv.y+bv.y; pb[2]=xv.z+bv.z; pb[3]=xv.w+bv.w;
        #pragma unroll
        for (int k = 0; k < 4; k++){
            sf += pf[k]; qf += pf[k]*pf[k];
            sb += pb[k]; qb += pb[k]*pb[k];
        }
    }
    #pragma unroll
    for (int o = 16; o; o >>= 1){
        sf += __shfl_xor_sync(0xffffffffu, sf, o);
        qf += __shfl_xor_sync(0xffffffffu, qf, o);
        sb += __shfl_xor_sync(0xffffffffu, sb, o);
        qb += __shfl_xor_sync(0xffffffffu, qb, o);
    }
    const float inv = 1.f / DMODEL;
    float muf = sf*inv, mub = sb*inv;
    float rsf = rsqrtf(qf*inv - muf*muf + 1e-5f);
    float rsb = rsqrtf(qb*inv - mub*mub + 1e-5f);

    float* hr = g_h + row * DMODEL;
    #pragma unroll
    for (int jj = 0; jj < 4; jj++){
        int col = lane*4 + jj*128;
        float4 gfv = *(const float4*)(gf + col);
        float4 bfv = *(const float4*)(bf + col);
        float4 gbv = *(const float4*)(gb + col);
        float4 bbv = *(const float4*)(bb + col);
        const float* pf = &af[jj*4]; const float* pb = &ab[jj*4];
        float4 o;
        o.x = 0.5f*(((pf[0]-muf)*rsf)*gfv.x + bfv.x + ((pb[0]-mub)*rsb)*gbv.x + bbv.x);
        o.y = 0.5f*(((pf[1]-muf)*rsf)*gfv.y + bfv.y + ((pb[1]-mub)*rsb)*gbv.y + bbv.y);
        o.z = 0.5f*(((pf[2]-muf)*rsf)*gfv.z + bfv.z + ((pb[2]-mub)*rsb)*gbv.z + bbv.z);
        o.w = 0.5f*(((pf[3]-muf)*rsf)*gfv.w + bfv.w + ((pb[3]-mub)*rsb)*gbv.w + bbv.w);
        *(float4*)(hr + col) = o;
    }
}

// ---------------- final: out = LN(h + ffo; ln_ff) ----------------
__global__ __launch_bounds__(256)
void final_ln_kernel(float* __restrict__ out,
                     const float* __restrict__ g, const float* __restrict__ bp)
{
    const int warp = threadIdx.x >> 5, lane = threadIdx.x & 31;
    const size_t row = (size_t)blockIdx.x * 8 + warp;
    const float* hr = g_h   + row * DMODEL;
    const float* fr = g_ffo + row * DMODEL;

    float a[16];
    float s = 0.f, q = 0.f;
    #pragma unroll
    for (int jj = 0; jj < 4; jj++){
        int col = lane*4 + jj*128;
        float4 hv = *(const float4*)(hr + col);
        float4 fv = *(const float4*)(fr + col);
        float* p = &a[jj*4];
        p[0]=hv.x+fv.x; p[1]=hv.y+fv.y; p[2]=hv.z+fv.z; p[3]=hv.w+fv.w;
        #pragma unroll
        for (int k = 0; k < 4; k++){ s += p[k]; q += p[k]*p[k]; }
    }
    #pragma unroll
    for (int o = 16; o; o >>= 1){
        s += __shfl_xor_sync(0xffffffffu, s, o);
        q += __shfl_xor_sync(0xffffffffu, q, o);
    }
    const float inv = 1.f / DMODEL;
    float mu = s*inv;
    float rs = rsqrtf(q*inv - mu*mu + 1e-5f);

    float* orow = out + row * DMODEL;
    #pragma unroll
    for (int jj = 0; jj < 4; jj++){
        int col = lane*4 + jj*128;
        float4 gv = *(const float4*)(g + col);
        float4 bv = *(const float4*)(bp + col);
        const float* p = &a[jj*4];
        float4 o;
        o.x = (p[0]-mu)*rs*gv.x + bv.x;
        o.y = (p[1]-mu)*rs*gv.y + bv.y;
        o.z = (p[2]-mu)*rs*gv.z + bv.z;
        o.w = (p[3]-mu)*rs*gv.w + bv.w;
        *(float4*)(orow + col) = o;
    }
}

// ---------------- launcher ----------------
extern "C" void kernel_launch(void* const* d_in, const int* in_sizes, int n_in,
                              void* d_out, int out_size)
{
    const float* x        = (const float*)d_in[0];
    const float* f_in_w   = (const float*)d_in[1];
    const float* f_conv_w = (const float*)d_in[2];
    const float* f_conv_b = (const float*)d_in[3];
    const float* f_xproj  = (const float*)d_in[4];
    const float* f_dt_w   = (const float*)d_in[5];
    const float* f_dt_b   = (const float*)d_in[6];
    const float* f_A_log  = (const float*)d_in[7];
    const float* f_D      = (const float*)d_in[8];
    const float* f_out_w  = (const float*)d_in[9];
    const float* b_in_w   = (const float*)d_in[10];
    const float* b_conv_w = (const float*)d_in[11];
    const float* b_conv_b = (const float*)d_in[12];
    const float* b_xproj  = (const float*)d_in[13];
    const float* b_dt_w   = (const float*)d_in[14];
    const float* b_dt_b   = (const float*)d_in[15];
    const float* b_A_log  = (const float*)d_in[16];
    const float* b_D      = (const float*)d_in[17];
    const float* b_out_w  = (const float*)d_in[18];
    const float* ln_f_g   = (const float*)d_in[19];
    const float* ln_f_b   = (const float*)d_in[20];
    const float* ln_b_g   = (const float*)d_in[21];
    const float* ln_b_b   = (const float*)d_in[22];
    const float* ln_ff_g  = (const float*)d_in[23];
    const float* ln_ff_b  = (const float*)d_in[24];
    const float* ffn_w1   = (const float*)d_in[25];
    const float* ffn_b1   = (const float*)d_in[26];
    const float* ffn_w2   = (const float*)d_in[27];
    const float* ffn_b2   = (const float*)d_in[28];

    float *p_xz, *p_xc, *p_dbc, *p_gated, *p_m, *p_h, *p_ff, *p_ffo;
    cudaGetSymbolAddress((void**)&p_xz,    g_xz);
    cudaGetSymbolAddress((void**)&p_xc,    g_xc);
    cudaGetSymbolAddress((void**)&p_dbc,   g_dbc);
    cudaGetSymbolAddress((void**)&p_gated, g_gated);
    cudaGetSymbolAddress((void**)&p_m,     g_m);
    cudaGetSymbolAddress((void**)&p_h,     g_h);
    cudaGetSymbolAddress((void**)&p_ff,    g_ff);
    cudaGetSymbolAddress((void**)&p_ffo,   g_ffo);

    __nv_bfloat16 *p_x3, *p_xc3, *p_g3, *p_h3, *p_ff3;
    __nv_bfloat16 *p_win3, *p_wxp3, *p_wou3, *p_wf13, *p_wf23;
    cudaGetSymbolAddress((void**)&p_x3,   g_x3);
    cudaGetSymbolAddress((void**)&p_xc3,  g_xc3);
    cudaGetSymbolAddress((void**)&p_g3,   g_g3);
    cudaGetSymbolAddress((void**)&p_h3,   g_h3);
    cudaGetSymbolAddress((void**)&p_ff3,  g_ff3);
    cudaGetSymbolAddress((void**)&p_win3, g_win3);
    cudaGetSymbolAddress((void**)&p_wxp3, g_wxp3);
    cudaGetSymbolAddress((void**)&p_wou3, g_wou3);
    cudaGetSymbolAddress((void**)&p_wf13, g_wf13);
    cudaGetSymbolAddress((void**)&p_wf23, g_wf23);

    // 0) weight splits (B operand layout [hi|lo|hi])
    split3_kernel<1><<<dim3(DMODEL/256, 2048, 2), 256>>>(f_in_w, b_in_w, p_win3, p_win3 + SZ_WIN3, DMODEL);
    split3_kernel<1><<<dim3(DINNER/256, 64, 2),   256>>>(f_xproj, b_xproj, p_wxp3, p_wxp3 + SZ_WXP3, DINNER);
    split3_kernel<1><<<dim3(DINNER/256, 512, 2),  256>>>(f_out_w, b_out_w, p_wou3, p_wou3 + SZ_WOU3, DINNER);
    split3_kernel<1><<<dim3(DMODEL/256, 2048, 1), 256>>>(ffn_w1, ffn_w1, p_wf13, p_wf13, DMODEL);
    split3_kernel<1><<<dim3(DFF/256,    512, 1),  256>>>(ffn_w2, ffn_w2, p_wf23, p_wf23, DFF);

    // 1) x split (A layout [hi|hi|lo]) + in_proj both dirs: xz = x @ in_w^T
    split3_kernel<0><<<dim3(DMODEL/256, MROWS, 1), 256>>>(x, x, p_x3, p_x3, DMODEL);
    mma_gemm_kernel<128,0><<<dim3(2048/128, MROWS/128, 2), 256>>>(
        p_x3, p_x3, p_win3, p_win3 + SZ_WIN3, p_xz, p_xz + SZ_XZ, nullptr, nullptr,
        2048, 3*DMODEL);

    // 2) depthwise conv + silu (both dirs)
    conv_silu_kernel<<<dim3(4, MROWS, 2), 256>>>(f_conv_w, f_conv_b, b_conv_w, b_conv_b);

    // 3) xc split + dbc = xc @ xproj^T  [32768,64]
    split3_kernel<0><<<dim3(DINNER/256, MROWS, 2), 256>>>(
        p_xc, p_xc + SZ_XC, p_xc3, p_xc3 + SZ_XC3, DINNER);
    mma_gemm_kernel<64,0><<<dim3(1, MROWS/128, 2), 256>>>(
        p_xc3, p_xc3 + SZ_XC3, p_wxp3, p_wxp3 + SZ_WXP3, p_dbc, p_dbc + SZ_DBC,
        nullptr, nullptr, 64, 3*DINNER);

    // 4) fused dt-proj + softplus + selective scan + D-skip + z-gate
    scan_kernel<<<dim3(16, BATCH, 2), 256>>>(
        f_dt_w, f_dt_b, f_A_log, f_D, b_dt_w, b_dt_b, b_A_log, b_D);

    // 5) gated split + out_proj: m = gated @ out_w^T  [32768,512]
    split3_kernel<0><<<dim3(DINNER/256, MROWS, 2), 256>>>(
        p_gated, p_gated + SZ_GATED, p_g3, p_g3 + SZ_G3, DINNER);
    mma_gemm_kernel<128,0><<<dim3(512/128, MROWS/128, 2), 256>>>(
        p_g3, p_g3 + SZ_G3, p_wou3, p_wou3 + SZ_WOU3, p_m, p_m + SZ_M,
        nullptr, nullptr, 512, 3*DINNER);

    // 6) h = 0.5*(LN(x+mf) + LN(x+mb))
    combine_ln_kernel<<<MROWS/8, 256>>>(x, ln_f_g, ln_f_b, ln_b_g, ln_b_b);

    // 7) h split + ff = gelu(h @ w1^T + b1)  [32768,2048]
    split3_kernel<0><<<dim3(DMODEL/256, MROWS, 1), 256>>>(p_h, p_h, p_h3, p_h3, DMODEL);
    mma_gemm_kernel<128,2><<<dim3(2048/128, MROWS/128, 1), 256>>>(
        p_h3, p_h3, p_wf13, p_wf13, p_ff, p_ff, ffn_b1, ffn_b1,
        2048, 3*DMODEL);

    // 8) ff split + ffo = ff @ w2^T + b2  [32768,512]
    split3_kernel<0><<<dim3(DFF/256, MROWS, 1), 256>>>(p_ff, p_ff, p_ff3, p_ff3, DFF);
    mma_gemm_kernel<128,1><<<dim3(512/128, MROWS/128, 1), 256>>>(
        p_ff3, p_ff3, p_wf23, p_wf23, p_ffo, p_ffo, ffn_b2, ffn_b2,
        512, 3*DFF);

    // 9) out = LN(h + ffo)
    final_ln_kernel<<<MROWS/8, 256>>>((float*)d_out, ln_ff_g, ln_ff_b);
}

// round 17
// speedup vs baseline: 1.1485x; 1.1485x over previous
#include <cuda_runtime.h>
#include <cuda_bf16.h>
#include <math.h>
#include <stdint.h>
#include <stddef.h>

// ---------------- problem constants ----------------
#define DMODEL 512
#define DINNER 1024
#define DSTATE 16
#define DTRANK 32
#define DFF    2048
#define BATCH  8
#define SEQ    4096
#define MROWS  (BATCH*SEQ)        // 32768

// ---------------- fp32 scratch ----------------
static const size_t SZ_XZ    = (size_t)MROWS * 2 * DINNER;
static const size_t SZ_XC    = (size_t)MROWS * DINNER;
static const size_t SZ_DBC   = (size_t)MROWS * 64;
static const size_t SZ_GATED = (size_t)MROWS * DINNER;
static const size_t SZ_M     = (size_t)MROWS * DMODEL;

__device__ float g_xz   [2ull * 67108864ull];
__device__ float g_xc   [2ull * 33554432ull];
__device__ float g_dbc  [2ull * 2097152ull];
__device__ float g_gated[2ull * 33554432ull];
__device__ float g_m    [2ull * 16777216ull];
__device__ float g_h    [16777216ull];
__device__ float g_ff   [67108864ull];
__device__ float g_ffo  [16777216ull];

// ---------------- bf16 split scratch (K' = 3K: A=[hi|hi|lo], B=[hi|lo|hi]) ----
__device__ __nv_bfloat16 g_x3   [50331648ull];            // 32768 x 1536
__device__ __nv_bfloat16 g_xc3  [2ull * 100663296ull];    // 32768 x 3072 per dir
__device__ __nv_bfloat16 g_g3   [2ull * 100663296ull];    // 32768 x 3072 per dir
__device__ __nv_bfloat16 g_h3   [50331648ull];            // 32768 x 1536
__device__ __nv_bfloat16 g_ff3  [201326592ull];           // 32768 x 6144
__device__ __nv_bfloat16 g_win3 [2ull * 3145728ull];      // 2048 x 1536
__device__ __nv_bfloat16 g_wxp3 [2ull * 196608ull];       // 64 x 3072
__device__ __nv_bfloat16 g_wou3 [2ull * 1572864ull];      // 512 x 3072
__device__ __nv_bfloat16 g_wf13 [3145728ull];             // 2048 x 1536
__device__ __nv_bfloat16 g_wf23 [3145728ull];             // 512 x 6144

static const size_t SZ_XC3 = 100663296ull;
static const size_t SZ_G3  = 100663296ull;
static const size_t SZ_WIN3 = 3145728ull;
static const size_t SZ_WXP3 = 196608ull;
static const size_t SZ_WOU3 = 1572864ull;

// ---------------- helpers ----------------
__device__ __forceinline__ float siluf(float v){
    return v / (1.f + __expf(-v));
}
__device__ __forceinline__ float gelu_tanh(float v){
    float u = 0.7978845608028654f * (v + 0.044715f * v * v * v);
    return 0.5f * v * (1.f + tanhf(u));
}

// mma.sync m16n8k16 bf16 -> f32 (baseline PTX, compiles for compute_103).
__device__ __forceinline__ void mma16816(float* d,
                                         const uint32_t* a, const uint32_t* b,
                                         const float* c)
{
    asm volatile(
        "mma.sync.aligned.m16n8k16.row.col.f32.bf16.bf16.f32 "
        "{%0,%1,%2,%3}, {%4,%5,%6,%7}, {%8,%9}, {%10,%11,%12,%13};\n"
        : "=f"(d[0]), "=f"(d[1]), "=f"(d[2]), "=f"(d[3])
        : "r"(a[0]), "r"(a[1]), "r"(a[2]), "r"(a[3]),
          "r"(b[0]), "r"(b[1]),
          "f"(c[0]), "f"(c[1]), "f"(c[2]), "f"(c[3]));
}

// ldmatrix x4 (sm_75+ baseline)
__device__ __forceinline__ void ldsm_x4(uint32_t* r, uint32_t saddr)
{
    asm volatile(
        "ldmatrix.sync.aligned.m8n8.x4.shared.b16 {%0,%1,%2,%3}, [%4];\n"
        : "=r"(r[0]), "=r"(r[1]), "=r"(r[2]), "=r"(r[3]) : "r"(saddr));
}

// cp.async 16B (sm_80 baseline)
__device__ __forceinline__ void cp_async16(uint32_t s_dst, const void* g_src)
{
    asm volatile("cp.async.cg.shared.global [%0], [%1], 16;\n"
                 :: "r"(s_dst), "l"(g_src));
}
#define CP_ASYNC_COMMIT() asm volatile("cp.async.commit_group;\n" ::: "memory")
#define CP_ASYNC_WAIT0()  asm volatile("cp.async.wait_group 0;\n" ::: "memory")

// ---------------- split3: fp32 [R][K] -> bf16 [R][3K], vectorized x4 ----------
// MODE 0 (A operand): [hi | hi | lo].  MODE 1 (B operand): [hi | lo | hi].
// 128 threads, each handles 4 consecutive elems; grid.x = K/512.
template<int MODE>
__global__ __launch_bounds__(128)
void split3_kernel(const float* __restrict__ s0, const float* __restrict__ s1,
                   __nv_bfloat16* __restrict__ d0, __nv_bfloat16* __restrict__ d1,
                   int K)
{
    const float* src = blockIdx.z ? s1 : s0;
    __nv_bfloat16* dst = blockIdx.z ? d1 : d0;
    const int k = (blockIdx.x * 128 + threadIdx.x) * 4;
    const size_t r = blockIdx.y;
    float4 v = *(const float4*)(src + r * K + k);

    __nv_bfloat16 h0 = __float2bfloat16(v.x);
    __nv_bfloat16 h1 = __float2bfloat16(v.y);
    __nv_bfloat16 h2 = __float2bfloat16(v.z);
    __nv_bfloat16 h3 = __float2bfloat16(v.w);
    __nv_bfloat16 l0 = __float2bfloat16(v.x - __bfloat162float(h0));
    __nv_bfloat16 l1 = __float2bfloat16(v.y - __bfloat162float(h1));
    __nv_bfloat16 l2 = __float2bfloat16(v.z - __bfloat162float(h2));
    __nv_bfloat16 l3 = __float2bfloat16(v.w - __bfloat162float(h3));

    __nv_bfloat162 hA = __halves2bfloat162(h0, h1);
    __nv_bfloat162 hB = __halves2bfloat162(h2, h3);
    __nv_bfloat162 lA = __halves2bfloat162(l0, l1);
    __nv_bfloat162 lB = __halves2bfloat162(l2, l3);
    uint2 hv = make_uint2(*(uint32_t*)&hA, *(uint32_t*)&hB);
    uint2 lv = make_uint2(*(uint32_t*)&lA, *(uint32_t*)&lB);

    size_t o = r * (size_t)(3 * K);
    if (MODE == 0){
        *(uint2*)(dst + o + k)       = hv;
        *(uint2*)(dst + o + K + k)   = hv;
        *(uint2*)(dst + o + 2*K + k) = lv;
    } else {
        *(uint2*)(dst + o + k)       = hv;
        *(uint2*)(dst + o + K + k)   = lv;
        *(uint2*)(dst + o + 2*K + k) = hv;
    }
}

// ---------------- mma.sync bf16 GEMM: C[M,N](f32) = A3[M,K3] * B3[N,K3]^T ----
// BM=128, BN in {128,64}, BK=32. 256 threads = 8 warps (4m x 2n).
// cp.async double-buffered (1 sync per k-tile), ldmatrix fragment loads.
// SMEM row stride 40 bf16 (80B) -> conflict-free ldmatrix phases.
// blockIdx.z selects operand set. EPI: 0 none, 1 +bias, 2 +bias+gelu.
template<int BN, int EPI>
__global__ __launch_bounds__(256)
void mma_gemm_kernel(const __nv_bfloat16* __restrict__ A0, const __nv_bfloat16* __restrict__ A1,
                     const __nv_bfloat16* __restrict__ B0, const __nv_bfloat16* __restrict__ B1,
                     float* __restrict__ C0, float* __restrict__ C1,
                     const float* __restrict__ bias0, const float* __restrict__ bias1,
                     int N, int K3)
{
    constexpr int BM = 128;
    constexpr int BK = 32;
    constexpr int STR = 40;                 // smem row stride in bf16 (80B)
    constexpr int WN  = BN / 2;             // warp n-width (64 or 32)
    constexpr int NT  = WN / 8;             // n-tiles per warp (8 or 4)
    constexpr int ALD = 2;                  // cp.async per thread (A tile)
    constexpr int BLD = (BN * BK) / (8 * 256);  // cp.async per thread (B tile)

    __shared__ __align__(16) __nv_bfloat16 sA[2][BM * STR];
    __shared__ __align__(16) __nv_bfloat16 sB[2][BN * STR];

    const int z = blockIdx.z;
    const __nv_bfloat16* A = z ? A1 : A0;
    const __nv_bfloat16* B = z ? B1 : B0;
    float*               C = z ? C1 : C0;
    const float*      bias = z ? bias1 : bias0;

    const int tid  = threadIdx.x;
    const int wid  = tid >> 5;
    const int lane = tid & 31;
    const int wm   = wid & 3;               // warp m index (0..3)
    const int wn   = wid >> 2;              // warp n index (0..1)
    const int m0 = blockIdx.y * BM;
    const int n0 = blockIdx.x * BN;

    uint32_t sA_u[2], sB_u[2];
    sA_u[0] = (uint32_t)__cvta_generic_to_shared(sA[0]);
    sA_u[1] = (uint32_t)__cvta_generic_to_shared(sA[1]);
    sB_u[0] = (uint32_t)__cvta_generic_to_shared(sB[0]);
    sB_u[1] = (uint32_t)__cvta_generic_to_shared(sB[1]);

    // cp.async staging maps (coalesced 16B granules)
    const int cr = tid >> 2;                 // row within tile group
    const int cc8 = (tid & 3) * 8;           // elem offset (16B granule)

    auto loadA = [&](int buf, int k0){
        #pragma unroll
        for (int i = 0; i < ALD; i++){
            int r = cr + i * 64;             // 0..127
            cp_async16(sA_u[buf] + (uint32_t)((r * STR + cc8) * 2),
                       A + (size_t)(m0 + r) * K3 + k0 + cc8);
        }
    };
    auto loadB = [&](int buf, int k0){
        #pragma unroll
        for (int i = 0; i < BLD; i++){
            int r = cr + i * 64;             // 0..BN-1
            cp_async16(sB_u[buf] + (uint32_t)((r * STR + cc8) * 2),
                       B + (size_t)(n0 + r) * K3 + k0 + cc8);
        }
    };

    float acc[2][NT][4];
    #pragma unroll
    for (int mt = 0; mt < 2; mt++)
        #pragma unroll
        for (int nt = 0; nt < NT; nt++)
            #pragma unroll
            for (int i = 0; i < 4; i++) acc[mt][nt][i] = 0.f;

    // ldmatrix lane address components
    const int a_row = lane & 15;             // 16 rows
    const int a_koff = (lane >> 4) * 8;      // k half select
    const int b_row = (lane & 7) + ((lane >> 3) & 1) * 8;  // 16 n-rows (paired tiles)
    const int b_koff = (lane >> 4) * 8;

    // prologue
    loadA(0, 0); loadB(0, 0); CP_ASYNC_COMMIT();
    CP_ASYNC_WAIT0(); __syncthreads();

    const int ktiles = K3 / BK;
    for (int t = 0; t < ktiles; t++){
        const int cur = t & 1, nxt = cur ^ 1;
        if (t + 1 < ktiles){
            loadA(nxt, (t+1)*BK); loadB(nxt, (t+1)*BK); CP_ASYNC_COMMIT();
        }

        const uint32_t sAb = sA_u[cur];
        const uint32_t sBb = sB_u[cur];

        #pragma unroll
        for (int kk = 0; kk < 2; kk++){
            // A fragments for both m-tiles (one x4 each)
            uint32_t af[2][4];
            #pragma unroll
            for (int mt = 0; mt < 2; mt++){
                const int rb = wm * 32 + mt * 16;
                ldsm_x4(af[mt],
                        sAb + (uint32_t)(((rb + a_row) * STR + kk*16 + a_koff) * 2));
            }
            // B fragments, paired n-tiles per x4
            uint32_t bf[NT][2];
            #pragma unroll
            for (int ntp = 0; ntp < NT/2; ntp++){
                const int nb = wn * WN + ntp * 16;
                uint32_t q[4];
                ldsm_x4(q, sBb + (uint32_t)(((nb + b_row) * STR + kk*16 + b_koff) * 2));
                bf[2*ntp  ][0] = q[0];
                bf[2*ntp+1][0] = q[1];
                bf[2*ntp  ][1] = q[2];
                bf[2*ntp+1][1] = q[3];
            }
            #pragma unroll
            for (int nt = 0; nt < NT; nt++){
                mma16816(acc[0][nt], af[0], bf[nt], acc[0][nt]);
                mma16816(acc[1][nt], af[1], bf[nt], acc[1][nt]);
            }
        }

        if (t + 1 < ktiles){
            CP_ASYNC_WAIT0();
            __syncthreads();
        }
    }

    // ---- epilogue ----
    const int gid  = lane >> 2;
    const int tig2 = (lane & 3) * 2;
    #pragma unroll
    for (int mt = 0; mt < 2; mt++){
        const int row = m0 + wm * 32 + mt * 16 + gid;
        #pragma unroll
        for (int nt = 0; nt < NT; nt++){
            const int col = n0 + wn * WN + nt * 8 + tig2;
            float v0 = acc[mt][nt][0], v1 = acc[mt][nt][1];
            float v2 = acc[mt][nt][2], v3 = acc[mt][nt][3];
            if (EPI >= 1){
                float b0 = __ldg(&bias[col]), b1 = __ldg(&bias[col + 1]);
                v0 += b0; v1 += b1; v2 += b0; v3 += b1;
            }
            if (EPI == 2){
                v0 = gelu_tanh(v0); v1 = gelu_tanh(v1);
                v2 = gelu_tanh(v2); v3 = gelu_tanh(v3);
            }
            float2 lo; lo.x = v0; lo.y = v1;
            float2 hi; hi.x = v2; hi.y = v3;
            *(float2*)(C + (size_t)row * N + col)       = lo;
            *(float2*)(C + (size_t)(row + 8) * N + col) = hi;
        }
    }
}

// ---------------- depthwise causal/anticausal conv(4) + bias + silu ----------------
__global__ __launch_bounds__(256)
void conv_silu_kernel(const float* __restrict__ cw0, const float* __restrict__ cb0,
                      const float* __restrict__ cw1, const float* __restrict__ cb1)
{
    const int c   = blockIdx.x * 256 + threadIdx.x;
    const int m   = blockIdx.y;
    const int dir = blockIdx.z;
    const float* cw = dir ? cw1 : cw0;
    const float* cb = dir ? cb1 : cb0;
    const float* xz = g_xz + (size_t)dir * SZ_XZ;

    const int b = m >> 12;
    const int l = m & (SEQ - 1);

    float w[4];
    #pragma unroll
    for (int j = 0; j < 4; j++) w[j] = __ldg(&cw[c*4 + j]);

    float acc = __ldg(&cb[c]);
    const size_t rowbase = (size_t)(b * SEQ) * (2*DINNER) + c;
    if (dir == 0){
        #pragma unroll
        for (int j = 0; j < 4; j++){
            int li = l - 3 + j;
            if (li >= 0) acc = fmaf(w[j], xz[rowbase + (size_t)li * (2*DINNER)], acc);
        }
    } else {
        #pragma unroll
        for (int j = 0; j < 4; j++){
            int li = l + 3 - j;
            if (li < SEQ) acc = fmaf(w[j], xz[rowbase + (size_t)li * (2*DINNER)], acc);
        }
    }
    g_xc[(size_t)dir * SZ_XC + (size_t)m * DINNER + c] = siluf(acc);
}

// ---------------- selective scan (fused dt-proj + softplus + scan + D + z-gate) ----
__global__ __launch_bounds__(256)
void scan_kernel(const float* __restrict__ dtw0, const float* __restrict__ dtb0,
                 const float* __restrict__ alog0, const float* __restrict__ D0,
                 const float* __restrict__ dtw1, const float* __restrict__ dtb1,
                 const float* __restrict__ alog1, const float* __restrict__ D1)
{
    const int dir = blockIdx.z;
    const int b   = blockIdx.y;
    const int cg  = blockIdx.x;
    const int tid = threadIdx.x;
    const int chl = tid >> 2;
    const int sub = tid & 3;
    const int c   = cg * 64 + chl;

    const float* dtw  = dir ? dtw1  : dtw0;
    const float* dtb  = dir ? dtb1  : dtb0;
    const float* alog = dir ? alog1 : alog0;
    const float* Dp   = dir ? D1    : D0;

    float A[4], w[8];
    #pragma unroll
    for (int i = 0; i < 4; i++) A[i] = -__expf(__ldg(&alog[c*DSTATE + sub*4 + i]));
    #pragma unroll
    for (int i = 0; i < 8; i++) w[i] = __ldg(&dtw[c*DTRANK + sub*8 + i]);
    const float dtb_c = __ldg(&dtb[c]);
    const float Dc    = __ldg(&Dp[c]);

    const float* dbc = g_dbc   + (size_t)dir * SZ_DBC   + (size_t)(b*SEQ) * 64;
    const float* xcb = g_xc    + (size_t)dir * SZ_XC    + (size_t)(b*SEQ) * DINNER;
    const float* zp  = g_xz    + (size_t)dir * SZ_XZ    + (size_t)(b*SEQ) * (2*DINNER) + DINNER;
    float*       op  = g_gated + (size_t)dir * SZ_GATED + (size_t)(b*SEQ) * DINNER;

    __shared__ float s_dbc[8][64];
    __shared__ float s_xc [8][64];

    float h[4] = {0.f, 0.f, 0.f, 0.f};

    for (int t0 = 0; t0 < SEQ; t0 += 8){
        __syncthreads();
        #pragma unroll
        for (int i = 0; i < 2; i++){
            int lin = tid + i * 256;
            int r = lin >> 6, col = lin & 63;
            int t = t0 + r;
            int l = dir ? (SEQ - 1 - t) : t;
            s_dbc[r][col] = dbc[(size_t)l * 64 + col];
            s_xc [r][col] = xcb[(size_t)l * DINNER + cg*64 + col];
        }
        __syncthreads();

        #pragma unroll
        for (int r = 0; r < 8; r++){
            int t = t0 + r;
            int l = dir ? (SEQ - 1 - t) : t;

            float dtp = 0.f;
            #pragma unroll
            for (int i = 0; i < 8; i++) dtp = fmaf(s_dbc[r][sub*8 + i], w[i], dtp);
            dtp += __shfl_xor_sync(0xffffffffu, dtp, 1);
            dtp += __shfl_xor_sync(0xffffffffu, dtp, 2);

            float v  = dtp + dtb_c;
            float dt = (v > 15.f) ? v : __logf(1.f + __expf(v));
            float xt  = s_xc[r][chl];
            float dtx = dt * xt;

            float yp = 0.f;
            #pragma unroll
            for (int i = 0; i < 4; i++){
                int n = sub*4 + i;
                float dA = __expf(dt * A[i]);
                h[i] = fmaf(dA, h[i], dtx * s_dbc[r][32 + n]);
                yp   = fmaf(h[i], s_dbc[r][48 + n], yp);
            }
            yp += __shfl_xor_sync(0xffffffffu, yp, 1);
            yp += __shfl_xor_sync(0xffffffffu, yp, 2);

            if (sub == 0){
                float y  = fmaf(xt, Dc, yp);
                float zv = __ldg(zp + (size_t)l * (2*DINNER) + c);
                op[(size_t)l * DINNER + c] = y * siluf(zv);
            }
        }
    }
}

// ---------------- combine: h = 0.5*(LN(x+mf;f) + LN(x+mb;b)) ----------------
__global__ __launch_bounds__(256)
void combine_ln_kernel(const float* __restrict__ x,
                       const float* __restrict__ gf, const float* __restrict__ bf,
                       const float* __restrict__ gb, const float* __restrict__ bb)
{
    const int warp = threadIdx.x >> 5, lane = threadIdx.x & 31;
    const size_t row = (size_t)blockIdx.x * 8 + warp;
    const float* xr  = x + row * DMODEL;
    const float* mfr = g_m + row * DMODEL;
    const float* mbr = g_m + SZ_M + row * DMODEL;

    float af[16], ab[16];
    float sf = 0.f, qf = 0.f, sb = 0.f, qb = 0.f;
    #pragma unroll
    for (int jj = 0; jj < 4; jj++){
        int col = lane*4 + jj*128;
        float4 xv = *(const float4*)(xr  + col);
        float4 fv = *(const float4*)(mfr + col);
        float4 bv = *(const float4*)(mbr + col);
        float* pf = &af[jj*4]; float* pb = &ab[jj*4];
        pf[0]=xv.x+fv.x; pf[1]=xv.y+fv.y; pf[2]=xv.z+fv.z; pf[3]=xv.w+fv.w;
        pb[0]=xv.x+bv.x; pb[1]=xv.y+bv.y; pb[2]=xv.z+bv.z; pb[3]=xv.w+bv.w;
        #pragma unroll
        for (int k = 0; k < 4; k++){
            sf += pf[k]; qf += pf[k]*pf[k];
            sb += pb[k]; qb += pb[k]*pb[k];
        }
    }
    #pragma unroll
    for (int o = 16; o; o >>= 1){
        sf += __shfl_xor_sync(0xffffffffu, sf, o);
        qf += __shfl_xor_sync(0xffffffffu, qf, o);
        sb += __shfl_xor_sync(0xffffffffu, sb, o);
        qb += __shfl_xor_sync(0xffffffffu, qb, o);
    }
    const float inv = 1.f / DMODEL;
    float muf = sf*inv, mub = sb*inv;
    float rsf = rsqrtf(qf*inv - muf*muf + 1e-5f);
    float rsb = rsqrtf(qb*inv - mub*mub + 1e-5f);

    float* hr = g_h + row * DMODEL;
    #pragma unroll
    for (int jj = 0; jj < 4; jj++){
        int col = lane*4 + jj*128;
        float4 gfv = *(const float4*)(gf + col);
        float4 bfv = *(const float4*)(bf + col);
        float4 gbv = *(const float4*)(gb + col);
        float4 bbv = *(const float4*)(bb + col);
        const float* pf = &af[jj*4]; const float* pb = &ab[jj*4];
        float4 o;
        o.x = 0.5f*(((pf[0]-muf)*rsf)*gfv.x + bfv.x + ((pb[0]-mub)*rsb)*gbv.x + bbv.x);
        o.y = 0.5f*(((pf[1]-muf)*rsf)*gfv.y + bfv.y + ((pb[1]-mub)*rsb)*gbv.y + bbv.y);
        o.z = 0.5f*(((pf[2]-muf)*rsf)*gfv.z + bfv.z + ((pb[2]-mub)*rsb)*gbv.z + bbv.z);
        o.w = 0.5f*(((pf[3]-muf)*rsf)*gfv.w + bfv.w + ((pb[3]-mub)*rsb)*gbv.w + bbv.w);
        *(float4*)(hr + col) = o;
    }
}

// ---------------- final: out = LN(h + ffo; ln_ff) ----------------
__global__ __launch_bounds__(256)
void final_ln_kernel(float* __restrict__ out,
                     const float* __restrict__ g, const float* __restrict__ bp)
{
    const int warp = threadIdx.x >> 5, lane = threadIdx.x & 31;
    const size_t row = (size_t)blockIdx.x * 8 + warp;
    const float* hr = g_h   + row * DMODEL;
    const float* fr = g_ffo + row * DMODEL;

    float a[16];
    float s = 0.f, q = 0.f;
    #pragma unroll
    for (int jj = 0; jj < 4; jj++){
        int col = lane*4 + jj*128;
        float4 hv = *(const float4*)(hr + col);
        float4 fv = *(const float4*)(fr + col);
        float* p = &a[jj*4];
        p[0]=hv.x+fv.x; p[1]=hv.y+fv.y; p[2]=hv.z+fv.z; p[3]=hv.w+fv.w;
        #pragma unroll
        for (int k = 0; k < 4; k++){ s += p[k]; q += p[k]*p[k]; }
    }
    #pragma unroll
    for (int o = 16; o; o >>= 1){
        s += __shfl_xor_sync(0xffffffffu, s, o);
        q += __shfl_xor_sync(0xffffffffu, q, o);
    }
    const float inv = 1.f / DMODEL;
    float mu = s*inv;
    float rs = rsqrtf(q*inv - mu*mu + 1e-5f);

    float* orow = out + row * DMODEL;
    #pragma unroll
    for (int jj = 0; jj < 4; jj++){
        int col = lane*4 + jj*128;
        float4 gv = *(const float4*)(g + col);
        float4 bv = *(const float4*)(bp + col);
        const float* p = &a[jj*4];
        float4 o;
        o.x = (p[0]-mu)*rs*gv.x + bv.x;
        o.y = (p[1]-mu)*rs*gv.y + bv.y;
        o.z = (p[2]-mu)*rs*gv.z + bv.z;
        o.w = (p[3]-mu)*rs*gv.w + bv.w;
        *(float4*)(orow + col) = o;
    }
}

// ---------------- launcher ----------------
extern "C" void kernel_launch(void* const* d_in, const int* in_sizes, int n_in,
                              void* d_out, int out_size)
{
    const float* x        = (const float*)d_in[0];
    const float* f_in_w   = (const float*)d_in[1];
    const float* f_conv_w = (const float*)d_in[2];
    const float* f_conv_b = (const float*)d_in[3];
    const float* f_xproj  = (const float*)d_in[4];
    const float* f_dt_w   = (const float*)d_in[5];
    const float* f_dt_b   = (const float*)d_in[6];
    const float* f_A_log  = (const float*)d_in[7];
    const float* f_D      = (const float*)d_in[8];
    const float* f_out_w  = (const float*)d_in[9];
    const float* b_in_w   = (const float*)d_in[10];
    const float* b_conv_w = (const float*)d_in[11];
    const float* b_conv_b = (const float*)d_in[12];
    const float* b_xproj  = (const float*)d_in[13];
    const float* b_dt_w   = (const float*)d_in[14];
    const float* b_dt_b   = (const float*)d_in[15];
    const float* b_A_log  = (const float*)d_in[16];
    const float* b_D      = (const float*)d_in[17];
    const float* b_out_w  = (const float*)d_in[18];
    const float* ln_f_g   = (const float*)d_in[19];
    const float* ln_f_b   = (const float*)d_in[20];
    const float* ln_b_g   = (const float*)d_in[21];
    const float* ln_b_b   = (const float*)d_in[22];
    const float* ln_ff_g  = (const float*)d_in[23];
    const float* ln_ff_b  = (const float*)d_in[24];
    const float* ffn_w1   = (const float*)d_in[25];
    const float* ffn_b1   = (const float*)d_in[26];
    const float* ffn_w2   = (const float*)d_in[27];
    const float* ffn_b2   = (const float*)d_in[28];

    float *p_xz, *p_xc, *p_dbc, *p_gated, *p_m, *p_h, *p_ff, *p_ffo;
    cudaGetSymbolAddress((void**)&p_xz,    g_xz);
    cudaGetSymbolAddress((void**)&p_xc,    g_xc);
    cudaGetSymbolAddress((void**)&p_dbc,   g_dbc);
    cudaGetSymbolAddress((void**)&p_gated, g_gated);
    cudaGetSymbolAddress((void**)&p_m,     g_m);
    cudaGetSymbolAddress((void**)&p_h,     g_h);
    cudaGetSymbolAddress((void**)&p_ff,    g_ff);
    cudaGetSymbolAddress((void**)&p_ffo,   g_ffo);

    __nv_bfloat16 *p_x3, *p_xc3, *p_g3, *p_h3, *p_ff3;
    __nv_bfloat16 *p_win3, *p_wxp3, *p_wou3, *p_wf13, *p_wf23;
    cudaGetSymbolAddress((void**)&p_x3,   g_x3);
    cudaGetSymbolAddress((void**)&p_xc3,  g_xc3);
    cudaGetSymbolAddress((void**)&p_g3,   g_g3);
    cudaGetSymbolAddress((void**)&p_h3,   g_h3);
    cudaGetSymbolAddress((void**)&p_ff3,  g_ff3);
    cudaGetSymbolAddress((void**)&p_win3, g_win3);
    cudaGetSymbolAddress((void**)&p_wxp3, g_wxp3);
    cudaGetSymbolAddress((void**)&p_wou3, g_wou3);
    cudaGetSymbolAddress((void**)&p_wf13, g_wf13);
    cudaGetSymbolAddress((void**)&p_wf23, g_wf23);

    // 0) weight splits (B operand layout [hi|lo|hi]); grid.x = K/512, 128 thr
    split3_kernel<1><<<dim3(1, 2048, 2), 128>>>(f_in_w, b_in_w, p_win3, p_win3 + SZ_WIN3, DMODEL);
    split3_kernel<1><<<dim3(2, 64, 2),   128>>>(f_xproj, b_xproj, p_wxp3, p_wxp3 + SZ_WXP3, DINNER);
    split3_kernel<1><<<dim3(2, 512, 2),  128>>>(f_out_w, b_out_w, p_wou3, p_wou3 + SZ_WOU3, DINNER);
    split3_kernel<1><<<dim3(1, 2048, 1), 128>>>(ffn_w1, ffn_w1, p_wf13, p_wf13, DMODEL);
    split3_kernel<1><<<dim3(4, 512, 1),  128>>>(ffn_w2, ffn_w2, p_wf23, p_wf23, DFF);

    // 1) x split (A layout [hi|hi|lo]) + in_proj both dirs: xz = x @ in_w^T
    split3_kernel<0><<<dim3(1, MROWS, 1), 128>>>(x, x, p_x3, p_x3, DMODEL);
    mma_gemm_kernel<128,0><<<dim3(2048/128, MROWS/128, 2), 256>>>(
        p_x3, p_x3, p_win3, p_win3 + SZ_WIN3, p_xz, p_xz + SZ_XZ, nullptr, nullptr,
        2048, 3*DMODEL);

    // 2) depthwise conv + silu (both dirs)
    conv_silu_kernel<<<dim3(4, MROWS, 2), 256>>>(f_conv_w, f_conv_b, b_conv_w, b_conv_b);

    // 3) xc split + dbc = xc @ xproj^T  [32768,64]
    split3_kernel<0><<<dim3(2, MROWS, 2), 128>>>(
        p_xc, p_xc + SZ_XC, p_xc3, p_xc3 + SZ_XC3, DINNER);
    mma_gemm_kernel<64,0><<<dim3(1, MROWS/128, 2), 256>>>(
        p_xc3, p_xc3 + SZ_XC3, p_wxp3, p_wxp3 + SZ_WXP3, p_dbc, p_dbc + SZ_DBC,
        nullptr, nullptr, 64, 3*DINNER);

    // 4) fused dt-proj + softplus + selective scan + D-skip + z-gate
    scan_kernel<<<dim3(16, BATCH, 2), 256>>>(
        f_dt_w, f_dt_b, f_A_log, f_D, b_dt_w, b_dt_b, b_A_log, b_D);

    // 5) gated split + out_proj: m = gated @ out_w^T  [32768,512]
    split3_kernel<0><<<dim3(2, MROWS, 2), 128>>>(
        p_gated, p_gated + SZ_GATED, p_g3, p_g3 + SZ_G3, DINNER);
    mma_gemm_kernel<128,0><<<dim3(512/128, MROWS/128, 2), 256>>>(
        p_g3, p_g3 + SZ_G3, p_wou3, p_wou3 + SZ_WOU3, p_m, p_m + SZ_M,
        nullptr, nullptr, 512, 3*DINNER);

    // 6) h = 0.5*(LN(x+mf) + LN(x+mb))
    combine_ln_kernel<<<MROWS/8, 256>>>(x, ln_f_g, ln_f_b, ln_b_g, ln_b_b);

    // 7) h split + ff = gelu(h @ w1^T + b1)  [32768,2048]
    split3_kernel<0><<<dim3(1, MROWS, 1), 128>>>(p_h, p_h, p_h3, p_h3, DMODEL);
    mma_gemm_kernel<128,2><<<dim3(2048/128, MROWS/128, 1), 256>>>(
        p_h3, p_h3, p_wf13, p_wf13, p_ff, p_ff, ffn_b1, ffn_b1,
        2048, 3*DMODEL);

    // 8) ff split + ffo = ff @ w2^T + b2  [32768,512]
    split3_kernel<0><<<dim3(4, MROWS, 1), 128>>>(p_ff, p_ff, p_ff3, p_ff3, DFF);
    mma_gemm_kernel<128,1><<<dim3(512/128, MROWS/128, 1), 256>>>(
        p_ff3, p_ff3, p_wf23, p_wf23, p_ffo, p_ffo, ffn_b2, ffn_b2,
        512, 3*DFF);

    // 9) out = LN(h + ffo)
    final_ln_kernel<<<MROWS/8, 256>>>((float*)d_out, ln_ff_g, ln_ff_b);
}